// round 7
// baseline (speedup 1.0000x reference)
#include <cuda_runtime.h>

// Problem constants (fixed by dataset: D=256, H=W=384, N=65536)
#define GH 384
#define GW 384
#define DCH 256
#define D4 (DCH / 4)   // 64 float4 per token row
#define NMAX 65536

// Scratch: (r,c) -> token index or -1. 384*384*4 = 576 KB.
__device__ int g_map[GH * GW];
// Per-token neighbor list: 9 tap slots (token idx or -1), padded to 12 ints.
__device__ int g_nbr[NMAX * 12];

__global__ void init_map_kernel() {
    int i = blockIdx.x * blockDim.x + threadIdx.x;
    int4* m4 = (int4*)g_map;
    if (i < (GH * GW) / 4) m4[i] = make_int4(-1, -1, -1, -1);
}

__global__ void scatter_map_kernel(const int* __restrict__ coords, int N) {
    int n = blockIdx.x * blockDim.x + threadIdx.x;
    if (n < N) {
        int r = coords[2 * n];
        int c = coords[2 * n + 1];
        g_map[r * GW + c] = n;
    }
}

// One thread per token: resolve the coords->map chain once, store 9 slots.
__global__ void build_nbr_kernel(const int* __restrict__ coords, int N) {
    int n = blockIdx.x * blockDim.x + threadIdx.x;
    if (n >= N) return;
    const int r = coords[2 * n];
    const int c = coords[2 * n + 1];
    int nb[12];
#pragma unroll
    for (int k = 0; k < 9; k++) {
        const int rr = r + (k / 3) - 1;
        const int cc = c + (k % 3) - 1;
        const bool ok = ((unsigned)rr < GH) && ((unsigned)cc < GW);
        int idx = ok ? (rr * GW + cc) : 0;
        int v = g_map[idx];
        nb[k] = ok ? v : -1;
    }
    nb[9] = nb[10] = nb[11] = -1;
    int4* dst = (int4*)(g_nbr + n * 12);
    dst[0] = make_int4(nb[0], nb[1], nb[2], nb[3]);
    dst[1] = make_int4(nb[4], nb[5], nb[6], nb[7]);
    dst[2] = make_int4(nb[8], nb[9], nb[10], nb[11]);
}

// Predicated gather: @p LDG.128 with zero-init destination — no branch, no
// memory traffic when the neighbor slot is empty.
__device__ __forceinline__ float4 ld_token_pred(const float4* __restrict__ base,
                                                int nb, int d4) {
    float4 t = make_float4(0.f, 0.f, 0.f, 0.f);
    const float4* p = base + (nb * D4 + d4);
    asm("{ .reg .pred p; setp.ge.s32 p, %5, 0;\n\t"
        "@p ld.global.nc.v4.f32 {%0,%1,%2,%3}, [%4]; }"
        : "+f"(t.x), "+f"(t.y), "+f"(t.z), "+f"(t.w)
        : "l"(p), "r"(nb));
    return t;
}

// Output layout (D, N): out[ch*N + n].
// Compute: 64-thread group per 8 tokens (2 batches of 4), 4 channels/thread.
// Tap-outer loop: one float4 of weights live at a time (from smem) -> low
// register pressure -> 4 CTAs/SM. Results staged via XOR-swizzled smem tile,
// then stored as warp-contiguous 128B lines along n.
__global__ __launch_bounds__(256, 4) void conv_gather_kernel(
    const float4* __restrict__ tokens,   // [N][64] float4
    const float*  __restrict__ weight,   // [256][9]
    const float4* __restrict__ bias4,    // [64] float4
    float*        __restrict__ out,      // [D][N]
    int N)
{
    __shared__ int    s_nbr[32 * 12];    // 32 tokens' neighbor lists
    __shared__ float4 s_w[9][64];        // weights: tap-major, contiguous in d4
    __shared__ float  s_out[32 * 256];   // 32 tokens x 256 channels (swizzled)

    const int tid = threadIdx.x;
    const int d4  = tid & 63;
    const int grp = tid >> 6;
    const int n0  = blockIdx.x * 32;

    for (int i = tid; i < 32 * 12; i += 256)
        s_nbr[i] = g_nbr[n0 * 12 + i];
    for (int idx = tid; idx < 9 * 64; idx += 256) {
        const int k = idx / 64, g = idx % 64;
        s_w[k][g] = make_float4(weight[(4 * g + 0) * 9 + k],
                                weight[(4 * g + 1) * 9 + k],
                                weight[(4 * g + 2) * 9 + k],
                                weight[(4 * g + 3) * 9 + k]);
    }
    const float4 b = bias4[d4];

    __syncthreads();

#pragma unroll
    for (int half = 0; half < 2; half++) {
        const int tb = grp * 8 + half * 4;          // token offset in block
        float4 acc0 = b, acc1 = b, acc2 = b, acc3 = b;
        const int* sl = s_nbr + tb * 12;
#pragma unroll
        for (int k = 0; k < 9; k++) {
            const float4 wk = s_w[k][d4];           // conflict-free LDS.128
            const int nb0 = sl[k];
            const int nb1 = sl[12 + k];
            const int nb2 = sl[24 + k];
            const int nb3 = sl[36 + k];
            const float4 t0 = ld_token_pred(tokens, nb0, d4);
            const float4 t1 = ld_token_pred(tokens, nb1, d4);
            const float4 t2 = ld_token_pred(tokens, nb2, d4);
            const float4 t3 = ld_token_pred(tokens, nb3, d4);
            acc0.x += wk.x * t0.x; acc0.y += wk.y * t0.y;
            acc0.z += wk.z * t0.z; acc0.w += wk.w * t0.w;
            acc1.x += wk.x * t1.x; acc1.y += wk.y * t1.y;
            acc1.z += wk.z * t1.z; acc1.w += wk.w * t1.w;
            acc2.x += wk.x * t2.x; acc2.y += wk.y * t2.y;
            acc2.z += wk.z * t2.z; acc2.w += wk.w * t2.w;
            acc3.x += wk.x * t3.x; acc3.y += wk.y * t3.y;
            acc3.z += wk.z * t3.z; acc3.w += wk.w * t3.w;
        }
        const int pg = d4 ^ (tb >> 2);              // swizzled float4 column
        ((float4*)s_out)[(tb + 0) * 64 + pg] = acc0;
        ((float4*)s_out)[(tb + 1) * 64 + pg] = acc1;
        ((float4*)s_out)[(tb + 2) * 64 + pg] = acc2;
        ((float4*)s_out)[(tb + 3) * 64 + pg] = acc3;
    }

    __syncthreads();

    // Store phase: 8 passes x (32 channels x 32 tokens). Each warp stores
    // 4 complete 128B lines (4 channels x 32 tokens x 4B).
    const int t4  = tid & 7;                        // token quad 0..7
    const int chb = tid >> 3;                       // 0..31
#pragma unroll
    for (int p = 0; p < 8; p++) {
        const int ch = p * 32 + chb;
        const int g  = ch >> 2;
        const int e  = ch & 3;
        const int pg = g ^ t4;
        float4 v;
        v.x = s_out[(4 * t4 + 0) * 256 + 4 * pg + e];
        v.y = s_out[(4 * t4 + 1) * 256 + 4 * pg + e];
        v.z = s_out[(4 * t4 + 2) * 256 + 4 * pg + e];
        v.w = s_out[(4 * t4 + 3) * 256 + 4 * pg + e];
        *(float4*)(out + (size_t)ch * N + n0 + 4 * t4) = v;
    }
}

extern "C" void kernel_launch(void* const* d_in, const int* in_sizes, int n_in,
                              void* d_out, int out_size) {
    // Identify inputs by element count (order-proof):
    //   tokens: 16777216 f32 | coords: 131072 i32 | weight: 2304 f32
    //   bias: 256 f32 | grid_h/grid_w: 1 i32 each (ignored)
    const float* tokens = nullptr;
    const int*   coords = nullptr;
    const float* weight = nullptr;
    const float* bias   = nullptr;
    int N = 65536;

    for (int i = 0; i < n_in; i++) {
        const int sz = in_sizes[i];
        if (sz >= DCH * 1024) {
            tokens = (const float*)d_in[i];
            N = sz / DCH;
        } else if (sz == 2304) {
            weight = (const float*)d_in[i];
        } else if (sz == DCH) {
            bias = (const float*)d_in[i];
        } else if (sz > DCH && sz < DCH * 1024) {
            coords = (const int*)d_in[i];
        }
    }

    float* out = (float*)d_out;

    init_map_kernel<<<(GH * GW / 4 + 255) / 256, 256>>>();
    scatter_map_kernel<<<(N + 255) / 256, 256>>>(coords, N);
    build_nbr_kernel<<<(N + 255) / 256, 256>>>(coords, N);

    conv_gather_kernel<<<(N + 31) / 32, 256>>>(
        (const float4*)tokens, weight, (const float4*)bias, out, N);
}

// round 9
// speedup vs baseline: 1.0491x; 1.0491x over previous
#include <cuda_runtime.h>

// Problem constants (fixed by dataset: D=256, H=W=384, N=65536)
#define GH 384
#define GW 384
#define DCH 256
#define D4 (DCH / 4)   // 64 float4 per token row
#define NMAX 65536

// Scratch: (r,c) -> token index or -1. 384*384*4 = 576 KB.
__device__ int g_map[GH * GW];
// Per-token neighbor list: 9 tap slots (token idx or -1), padded to 12 ints.
__device__ int g_nbr[NMAX * 12];

__global__ void init_map_kernel() {
    int i = blockIdx.x * blockDim.x + threadIdx.x;
    int4* m4 = (int4*)g_map;
    if (i < (GH * GW) / 4) m4[i] = make_int4(-1, -1, -1, -1);
}

__global__ void scatter_map_kernel(const int* __restrict__ coords, int N) {
    int n = blockIdx.x * blockDim.x + threadIdx.x;
    if (n < N) {
        int r = coords[2 * n];
        int c = coords[2 * n + 1];
        g_map[r * GW + c] = n;
    }
}

// One thread per token: resolve the coords->map chain once, store 9 slots.
__global__ void build_nbr_kernel(const int* __restrict__ coords, int N) {
    int n = blockIdx.x * blockDim.x + threadIdx.x;
    if (n >= N) return;
    const int r = coords[2 * n];
    const int c = coords[2 * n + 1];
    int nb[12];
#pragma unroll
    for (int k = 0; k < 9; k++) {
        const int rr = r + (k / 3) - 1;
        const int cc = c + (k % 3) - 1;
        const bool ok = ((unsigned)rr < GH) && ((unsigned)cc < GW);
        int idx = ok ? (rr * GW + cc) : 0;
        int v = g_map[idx];
        nb[k] = ok ? v : -1;
    }
    nb[9] = nb[10] = nb[11] = -1;
    int4* dst = (int4*)(g_nbr + n * 12);
    dst[0] = make_int4(nb[0], nb[1], nb[2], nb[3]);
    dst[1] = make_int4(nb[4], nb[5], nb[6], nb[7]);
    dst[2] = make_int4(nb[8], nb[9], nb[10], nb[11]);
}

// One evict_last cache policy per thread (createpolicy once, reuse for all
// gathers). ld...L2::cache_hint accepts any vector width, unlike the direct
// L2::evict_last modifier (which ptxas restricts to v8.b32/v4.b64).
__device__ __forceinline__ unsigned long long make_evict_last_policy() {
    unsigned long long pol;
    asm("createpolicy.fractional.L2::evict_last.b64 %0, 1.0;" : "=l"(pol));
    return pol;
}

// Predicated gather with L2 evict_last hint: token rows are re-read ~4.6x,
// keep them resident in L2. Zero-init dest, no branch, no traffic when empty.
__device__ __forceinline__ float4 ld_token_pred(const float4* __restrict__ base,
                                                int nb, int d4,
                                                unsigned long long pol) {
    float4 t = make_float4(0.f, 0.f, 0.f, 0.f);
    const float4* p = base + (nb * D4 + d4);
    asm("{ .reg .pred p; setp.ge.s32 p, %5, 0;\n\t"
        "@p ld.global.nc.L2::cache_hint.v4.f32 {%0,%1,%2,%3}, [%4], %6; }"
        : "+f"(t.x), "+f"(t.y), "+f"(t.z), "+f"(t.w)
        : "l"(p), "r"(nb), "l"(pol));
    return t;
}

// Streaming store: output is write-once — do not let it evict token lines.
__device__ __forceinline__ void st_stream(float4* p, float4 v) {
    asm volatile("st.global.cs.v4.f32 [%0], {%1,%2,%3,%4};"
                 :: "l"(p), "f"(v.x), "f"(v.y), "f"(v.z), "f"(v.w));
}

// Output layout (D, N): out[ch*N + n].
// Compute: 64-thread group per 8 tokens (2 batches of 4), 4 channels/thread.
// Tap-outer loop with smem weights -> low regs -> 4 CTAs/SM. Results staged
// via XOR-swizzled smem tile, stored as warp-contiguous 128B lines along n.
__global__ __launch_bounds__(256, 4) void conv_gather_kernel(
    const float4* __restrict__ tokens,   // [N][64] float4
    const float*  __restrict__ weight,   // [256][9]
    const float4* __restrict__ bias4,    // [64] float4
    float*        __restrict__ out,      // [D][N]
    int N)
{
    __shared__ int    s_nbr[32 * 12];    // 32 tokens' neighbor lists
    __shared__ float4 s_w[9][64];        // weights: tap-major, contiguous in d4
    __shared__ float  s_out[32 * 256];   // 32 tokens x 256 channels (swizzled)

    const int tid = threadIdx.x;
    const int d4  = tid & 63;
    const int grp = tid >> 6;
    const int n0  = blockIdx.x * 32;

    for (int i = tid; i < 32 * 12; i += 256)
        s_nbr[i] = g_nbr[n0 * 12 + i];
    for (int idx = tid; idx < 9 * 64; idx += 256) {
        const int k = idx / 64, g = idx % 64;
        s_w[k][g] = make_float4(weight[(4 * g + 0) * 9 + k],
                                weight[(4 * g + 1) * 9 + k],
                                weight[(4 * g + 2) * 9 + k],
                                weight[(4 * g + 3) * 9 + k]);
    }
    const float4 b = bias4[d4];
    const unsigned long long pol = make_evict_last_policy();

    __syncthreads();

#pragma unroll
    for (int half = 0; half < 2; half++) {
        const int tb = grp * 8 + half * 4;          // token offset in block
        float4 acc0 = b, acc1 = b, acc2 = b, acc3 = b;
        const int* sl = s_nbr + tb * 12;
#pragma unroll
        for (int k = 0; k < 9; k++) {
            const float4 wk = s_w[k][d4];           // conflict-free LDS.128
            const int nb0 = sl[k];
            const int nb1 = sl[12 + k];
            const int nb2 = sl[24 + k];
            const int nb3 = sl[36 + k];
            const float4 t0 = ld_token_pred(tokens, nb0, d4, pol);
            const float4 t1 = ld_token_pred(tokens, nb1, d4, pol);
            const float4 t2 = ld_token_pred(tokens, nb2, d4, pol);
            const float4 t3 = ld_token_pred(tokens, nb3, d4, pol);
            acc0.x += wk.x * t0.x; acc0.y += wk.y * t0.y;
            acc0.z += wk.z * t0.z; acc0.w += wk.w * t0.w;
            acc1.x += wk.x * t1.x; acc1.y += wk.y * t1.y;
            acc1.z += wk.z * t1.z; acc1.w += wk.w * t1.w;
            acc2.x += wk.x * t2.x; acc2.y += wk.y * t2.y;
            acc2.z += wk.z * t2.z; acc2.w += wk.w * t2.w;
            acc3.x += wk.x * t3.x; acc3.y += wk.y * t3.y;
            acc3.z += wk.z * t3.z; acc3.w += wk.w * t3.w;
        }
        const int pg = d4 ^ (tb >> 2);              // swizzled float4 column
        ((float4*)s_out)[(tb + 0) * 64 + pg] = acc0;
        ((float4*)s_out)[(tb + 1) * 64 + pg] = acc1;
        ((float4*)s_out)[(tb + 2) * 64 + pg] = acc2;
        ((float4*)s_out)[(tb + 3) * 64 + pg] = acc3;
    }

    __syncthreads();

    // Store phase: 8 passes x (32 channels x 32 tokens). Each warp stores
    // 4 complete 128B lines (4 channels x 32 tokens x 4B), streaming hint.
    const int t4  = tid & 7;                        // token quad 0..7
    const int chb = tid >> 3;                       // 0..31
#pragma unroll
    for (int p = 0; p < 8; p++) {
        const int ch = p * 32 + chb;
        const int g  = ch >> 2;
        const int e  = ch & 3;
        const int pg = g ^ t4;
        float4 v;
        v.x = s_out[(4 * t4 + 0) * 256 + 4 * pg + e];
        v.y = s_out[(4 * t4 + 1) * 256 + 4 * pg + e];
        v.z = s_out[(4 * t4 + 2) * 256 + 4 * pg + e];
        v.w = s_out[(4 * t4 + 3) * 256 + 4 * pg + e];
        st_stream((float4*)(out + (size_t)ch * N + n0 + 4 * t4), v);
    }
}

extern "C" void kernel_launch(void* const* d_in, const int* in_sizes, int n_in,
                              void* d_out, int out_size) {
    // Identify inputs by element count (order-proof):
    //   tokens: 16777216 f32 | coords: 131072 i32 | weight: 2304 f32
    //   bias: 256 f32 | grid_h/grid_w: 1 i32 each (ignored)
    const float* tokens = nullptr;
    const int*   coords = nullptr;
    const float* weight = nullptr;
    const float* bias   = nullptr;
    int N = 65536;

    for (int i = 0; i < n_in; i++) {
        const int sz = in_sizes[i];
        if (sz >= DCH * 1024) {
            tokens = (const float*)d_in[i];
            N = sz / DCH;
        } else if (sz == 2304) {
            weight = (const float*)d_in[i];
        } else if (sz == DCH) {
            bias = (const float*)d_in[i];
        } else if (sz > DCH && sz < DCH * 1024) {
            coords = (const int*)d_in[i];
        }
    }

    float* out = (float*)d_out;

    init_map_kernel<<<(GH * GW / 4 + 255) / 256, 256>>>();
    scatter_map_kernel<<<(N + 255) / 256, 256>>>(coords, N);
    build_nbr_kernel<<<(N + 255) / 256, 256>>>(coords, N);

    conv_gather_kernel<<<(N + 31) / 32, 256>>>(
        (const float4*)tokens, weight, (const float4*)bias, out, N);
}